// round 14
// baseline (speedup 1.0000x reference)
#include <cuda_runtime.h>

typedef unsigned long long ull;

#define NTOT 51840000   // 405*80*80*20

__device__ float g_mask1[6400];
__device__ float g_mask2[6400];

__global__ void mask_prep(const float* __restrict__ a1, const float* __restrict__ a2)
{
    int p = blockIdx.x * blockDim.x + threadIdx.x;
    if (p < 6400) {
        float s1 = 0.f, s2 = 0.f;
        const float* p1 = a1 + p * 20;
        const float* p2 = a2 + p * 20;
        #pragma unroll
        for (int z = 0; z < 20; ++z) { s1 += p1[z]; s2 += p2[z]; }
        g_mask1[p] = fminf(fmaxf(s1, 0.f), 1.f);
        g_mask2[p] = fminf(fmaxf(s2, 0.f), 1.f);
    }
}

__device__ __forceinline__ void unpack2(ull v, float& lo, float& hi) {
    asm("mov.b64 {%0, %1}, %2;" : "=f"(lo), "=f"(hi) : "l"(v));
}
__device__ __forceinline__ void fma2(ull& d, ull a, ull b) {
    asm("fma.rn.f32x2 %0, %1, %2, %0;" : "+l"(d) : "l"(a), "l"(b));
}
__device__ __forceinline__ ull shiftpair(ull a, ull b) {
    ull r;
    asm("{\n\t.reg .b32 alo, ahi, blo, bhi;\n\t"
        "mov.b64 {alo, ahi}, %1;\n\t"
        "mov.b64 {blo, bhi}, %2;\n\t"
        "mov.b64 %0, {ahi, blo};\n\t}"
        : "=l"(r) : "l"(a), "l"(b));
    return r;
}
__device__ __forceinline__ void cp16(unsigned dst, const void* src) {
    asm volatile("cp.async.cg.shared.global [%0], [%1], 16;" :: "r"(dst), "l"(src));
}
__device__ __forceinline__ void cp_commit() {
    asm volatile("cp.async.commit_group;" ::: "memory");
}
template<int N> __device__ __forceinline__ void cp_wait() {
    asm volatile("cp.async.wait_group %0;" :: "n"(N) : "memory");
}

// b-window for one channel (8 regs)
struct BW {
    ull q0hi;         // z 4zq-2..4zq-1
    ulonglong2 Q1;    // z 4zq..4zq+3
    ull q2lo;         // z 4zq+4..4zq+5
};

__device__ __forceinline__ void loadB(BW& b, const float* f2b, int cl, int bq0)
{
    const float* bp = f2b + (cl * 208 + bq0) * 4;
    b.q0hi = *(const ull*)(bp + 2);
    b.Q1   = *(const ulonglong2*)(bp + 4);
    b.q2lo = *(const ull*)(bp + 8);
}
__device__ __forceinline__ ulonglong2 loadA(const float* f1p, int cl, int aq)
{
    return *(const ulonglong2*)(f1p + (cl * 120 + aq) * 4);
}

// 10 fma2 for one (channel, jl): 5 dk x 2 z-pairs
__device__ __forceinline__ void fma10(ull* A, ulonglong2 a, const BW& b,
                                      ull P1, ull P3, ull P5)
{
    fma2(A[0], a.x, b.q0hi); fma2(A[1], a.y, b.Q1.x);   // dk=0
    fma2(A[2], a.x, P1    ); fma2(A[3], a.y, P3    );   // dk=1
    fma2(A[4], a.x, b.Q1.x); fma2(A[5], a.y, b.Q1.y);   // dk=2
    fma2(A[6], a.x, P3    ); fma2(A[7], a.y, P5    );   // dk=3
    fma2(A[8], a.x, b.Q1.y); fma2(A[9], a.y, b.q2lo);   // dk=4
}

// block: 240 threads, tid = zq + 5*x2c + 80*djg (zq fastest -> coalesced stores)
// grid : (x2b 6, y 80, di 9); dj = djg*3 + jl, x = x2g + 4 - dj
// f1 RESIDENT (single copy, filled once in prologue):
//   f1s [c32][xl24][q5] quads = 3840 q = 61440 B; xg = x2g0 + xl - 4, zero-pad
// f2 double-buffered, 4 phases x 8 channels:
//   f2 buf [c8][x2 16][13 quads] = 1664 q = 26624 B each; guard quads 0 & 6 zero,
//   quads 1..5 = z 0..19 (unshifted)
// smem = 61440 + 2*26624 = 114688 B (112 KB) -> 2 blocks/SM (224 KB <= 228 KB)
#define F1TOTQ 3840
#define F2B 26624
#define F2BASE 61440          // bytes
#define F2BASEQ 3840          // quads
#define CADV 1024000          // 8 channels * 128000 floats

__global__ void __launch_bounds__(240, 2) corr_kernel(
    const float* __restrict__ f1, const float* __restrict__ f2, float* __restrict__ out)
{
    extern __shared__ float smem[];
    const unsigned sb = (unsigned)__cvta_generic_to_shared(smem);

    const int x2b  = blockIdx.x;
    const int y    = blockIdx.y;
    const int di   = blockIdx.z;
    const int x2g0 = x2b * 16 - 4;
    const int y2   = y + di - 4;
    const bool yok = ((unsigned)y2 < 80u);
    const int tid  = threadIdx.x;

    const int zq  = tid % 5;
    const int x2c = (tid / 5) & 15;
    const int djg = tid / 80;
    const int x2g = x2g0 + x2c;

    // ---- f2 steady-state fill assignments (src offsets in floats; <0 = skip) ----
    int f2off[3]; unsigned f2dst[3];
    #pragma unroll
    for (int k = 0; k < 3; ++k) {
        int j = tid + 240 * k;              // 0..639 copies
        int i = j / 5;
        int m = j - i * 5;
        int c   = i >> 4;
        int x2l = i & 15;
        int x2  = x2g0 + x2l;
        f2dst[k] = sb + F2BASE + ((c * 16 + x2l) * 13 + 1 + m) * 16;
        f2off[k] = (j < 640 && yok && (unsigned)x2 < 80u)
                   ? (c * 128000 + y2 * 1600 + x2 * 20 + 4 * m) : (int)0x80000000;
    }

    // ---- zeroing: interior blocks only need f2 guard quads; edge blocks all ----
    if (yok) {
        float4 z4 = make_float4(0.f, 0.f, 0.f, 0.f);
        if (x2b == 0 || x2b == 5) {
            for (int i = tid; i < 7168; i += 240) ((float4*)smem)[i] = z4;
        } else {
            // 512 guard quads: 2 buffers x 8 c x 16 x2l x {quad 0, quad 6}
            for (int i = tid; i < 512; i += 240) {
                int e   = i & 255;
                int cx  = e >> 1;                  // c*16 + x2l  (0..127)
                int g   = (e & 1) * 6;
                int quad = F2BASEQ + (i >> 8) * (F2B / 16) + cx * 13 + g;
                ((float4*)smem)[quad] = z4;
            }
        }
    }
    __syncthreads();

    // ---- prologue: full f1 tile (all 32 channels) + f2 phase 0, one group ----
    if (yok) {
        #pragma unroll
        for (int k = 0; k < 16; ++k) {
            int idx = tid + 240 * k;        // 0..3839 quads
            int c  = idx / 120;
            int r  = idx - c * 120;
            int xl = r / 5;
            int q  = r - xl * 5;
            int xg = x2g0 + xl - 4;
            if ((unsigned)xg < 80u)
                cp16(sb + idx * 16,
                     f1 + c * 128000 + y * 1600 + xg * 20 + 4 * q);
        }
    }
    if (f2off[0] >= 0) cp16(f2dst[0], f2 + f2off[0]);
    if (f2off[1] >= 0) cp16(f2dst[1], f2 + f2off[1]);
    if (f2off[2] >= 0) cp16(f2dst[2], f2 + f2off[2]);
    cp_commit();

    ull acc[30];
    #pragma unroll
    for (int i = 0; i < 30; ++i) acc[i] = 0ull;

    const int aq0 = (x2c + 8 - djg * 3) * 5 + zq;   // f1 quad idx (jl subtracts 5)
    const int bq0 = x2c * 13 + zq;                  // f2 quad idx within channel

    #pragma unroll 2
    for (int p = 0; p < 4; ++p) {
        const int cur = p & 1;
        cp_wait<0>();          // phase-p f2 (and f1 on p=0) has arrived
        __syncthreads();       // visible to all; all finished compute(p-1) on buf[1-cur]
        // issue f2 phase p+1 into buf[1-cur] (safe: barrier above) — overlaps compute(p)
        if (p < 3) {
            const int adv = (p + 1) * CADV;
            const unsigned b2 = (1 - cur) * F2B;
            if (f2off[0] >= 0) cp16(f2dst[0] + b2, f2 + f2off[0] + adv);
            if (f2off[1] >= 0) cp16(f2dst[1] + b2, f2 + f2off[1] + adv);
            if (f2off[2] >= 0) cp16(f2dst[2] + b2, f2 + f2off[2] + adv);
            cp_commit();
        }

        if (yok) {
            const float* f1p = smem + p * 3840;   // this phase's 8 channels in f1s
            const float* f2b = smem + (F2BASE + cur * F2B) / 4;
            // operand pipeline: B ping-pong (distance 1 ch), A 3-slot JIT rotation
            BW B0, B1;
            ulonglong2 A0, A1, A2;
            loadB(B0, f2b, 0, bq0);
            A0 = loadA(f1p, 0, aq0);
            A1 = loadA(f1p, 0, aq0 - 5);
            A2 = loadA(f1p, 0, aq0 - 10);
            loadB(B1, f2b, 1, bq0);
            #pragma unroll
            for (int cl = 0; cl < 8; ++cl) {
                const BW& Bc = (cl & 1) ? B1 : B0;
                ull P1 = shiftpair(Bc.q0hi, Bc.Q1.x);
                ull P3 = shiftpair(Bc.Q1.x, Bc.Q1.y);
                ull P5 = shiftpair(Bc.Q1.y, Bc.q2lo);
                fma10(acc +  0, A0, Bc, P1, P3, P5);
                if (cl < 7) A0 = loadA(f1p, cl + 1, aq0);
                fma10(acc + 10, A1, Bc, P1, P3, P5);
                if (cl < 7) A1 = loadA(f1p, cl + 1, aq0 - 5);
                fma10(acc + 20, A2, Bc, P1, P3, P5);
                if (cl < 7) A2 = loadA(f1p, cl + 1, aq0 - 10);
                // refill the slot just consumed with channel cl+2
                if (cl < 6) loadB((cl & 1) ? B1 : B0, f2b, cl + 2, bq0);
            }
        }
    }

    // ---- epilogue: coalesced stores (z-fastest across lanes) ----
    // note: !spin => m2v = 1 => mIn == m1, so mask element = inrange ? mIn : m1
    {
        const bool x2ok = ((unsigned)x2g < 80u);
        const bool spin = yok && x2ok;
        const float m2v = spin ? g_mask2[y2 * 80 + x2g] : 1.f;
        const float inv = 1.f / 32.f;
        #pragma unroll
        for (int jl = 0; jl < 3; ++jl) {
            const int dj = djg * 3 + jl;
            const int x  = x2g + 4 - dj;
            if ((unsigned)x < 80u) {
                const float m1  = g_mask1[y * 80 + x];
                const float mIn = m1 * m2v;
                float* pc = out + (size_t)(di * 9 + dj) * 128000
                                + y * 1600 + x * 20 + 4 * zq;
                float* pm = pc + NTOT;
                #pragma unroll
                for (int dk = 0; dk < 5; ++dk) {
                    float4 cv;
                    unpack2(acc[jl * 10 + dk * 2 + 0], cv.x, cv.y);
                    unpack2(acc[jl * 10 + dk * 2 + 1], cv.z, cv.w);
                    cv.x *= inv; cv.y *= inv; cv.z *= inv; cv.w *= inv;
                    *(float4*)pc = cv;
                    float4 mv;
                    {
                        float* mp = (float*)&mv;
                        #pragma unroll
                        for (int zl = 0; zl < 4; ++zl) {
                            int z2 = 4 * zq + zl + dk - 2;
                            mp[zl] = ((unsigned)z2 < 20u) ? mIn : m1;
                        }
                    }
                    *(float4*)pm = mv;
                    pc += (size_t)81 * 128000;
                    pm += (size_t)81 * 128000;
                }
            }
        }
    }
}

extern "C" void kernel_launch(void* const* d_in, const int* in_sizes, int n_in,
                              void* d_out, int out_size)
{
    (void)in_sizes; (void)n_in; (void)out_size;
    const float* f1 = (const float*)d_in[0];
    const float* a1 = (const float*)d_in[1];
    const float* f2 = (const float*)d_in[2];
    const float* a2 = (const float*)d_in[3];
    float* out = (float*)d_out;

    cudaFuncSetAttribute(corr_kernel, cudaFuncAttributeMaxDynamicSharedMemorySize, 114688);

    mask_prep<<<25, 256>>>(a1, a2);
    corr_kernel<<<dim3(6, 80, 9), 240, 114688>>>(f1, f2, out);
}

// round 15
// speedup vs baseline: 1.0269x; 1.0269x over previous
#include <cuda_runtime.h>

typedef unsigned long long ull;

#define NTOT 51840000   // 405*80*80*20

__device__ float g_mask1[6400];
__device__ float g_mask2[6400];

__global__ void mask_prep(const float* __restrict__ a1, const float* __restrict__ a2)
{
    int p = blockIdx.x * blockDim.x + threadIdx.x;
    if (p < 6400) {
        float s1 = 0.f, s2 = 0.f;
        const float* p1 = a1 + p * 20;
        const float* p2 = a2 + p * 20;
        #pragma unroll
        for (int z = 0; z < 20; ++z) { s1 += p1[z]; s2 += p2[z]; }
        g_mask1[p] = fminf(fmaxf(s1, 0.f), 1.f);
        g_mask2[p] = fminf(fmaxf(s2, 0.f), 1.f);
    }
}

__device__ __forceinline__ void unpack2(ull v, float& lo, float& hi) {
    asm("mov.b64 {%0, %1}, %2;" : "=f"(lo), "=f"(hi) : "l"(v));
}
__device__ __forceinline__ void fma2(ull& d, ull a, ull b) {
    asm("fma.rn.f32x2 %0, %1, %2, %0;" : "+l"(d) : "l"(a), "l"(b));
}
__device__ __forceinline__ ull shiftpair(ull a, ull b) {
    ull r;
    asm("{\n\t.reg .b32 alo, ahi, blo, bhi;\n\t"
        "mov.b64 {alo, ahi}, %1;\n\t"
        "mov.b64 {blo, bhi}, %2;\n\t"
        "mov.b64 %0, {ahi, blo};\n\t}"
        : "=l"(r) : "l"(a), "l"(b));
    return r;
}
__device__ __forceinline__ void cp16(unsigned dst, const void* src) {
    asm volatile("cp.async.cg.shared.global [%0], [%1], 16;" :: "r"(dst), "l"(src));
}
__device__ __forceinline__ void cp_commit() {
    asm volatile("cp.async.commit_group;" ::: "memory");
}
template<int N> __device__ __forceinline__ void cp_wait() {
    asm volatile("cp.async.wait_group %0;" :: "n"(N) : "memory");
}

// b-window for one channel (8 regs)
struct BW {
    ull q0hi;         // z 4zq-2..4zq-1
    ulonglong2 Q1;    // z 4zq..4zq+3
    ull q2lo;         // z 4zq+4..4zq+5
};

__device__ __forceinline__ void loadB(BW& b, const float* f2b, int cl, int bq0)
{
    const float* bp = f2b + (cl * 208 + bq0) * 4;
    b.q0hi = *(const ull*)(bp + 2);
    b.Q1   = *(const ulonglong2*)(bp + 4);
    b.q2lo = *(const ull*)(bp + 8);
}
__device__ __forceinline__ ulonglong2 loadA(const float* f1p, int cl, int aq)
{
    return *(const ulonglong2*)(f1p + (cl * 120 + aq) * 4);
}

// 10 fma2 for one (channel, jl): 5 dk x 2 z-pairs
__device__ __forceinline__ void fma10(ull* A, ulonglong2 a, const BW& b,
                                      ull P1, ull P3, ull P5)
{
    fma2(A[0], a.x, b.q0hi); fma2(A[1], a.y, b.Q1.x);   // dk=0
    fma2(A[2], a.x, P1    ); fma2(A[3], a.y, P3    );   // dk=1
    fma2(A[4], a.x, b.Q1.x); fma2(A[5], a.y, b.Q1.y);   // dk=2
    fma2(A[6], a.x, P3    ); fma2(A[7], a.y, P5    );   // dk=3
    fma2(A[8], a.x, b.Q1.y); fma2(A[9], a.y, b.q2lo);   // dk=4
}

// block: 240 threads, tid = zq + 5*x2c + 80*djg (zq fastest -> coalesced stores)
// grid : (x2b 6, y 80, dig 3); block loops dil 0..2, di = dig*3 + dil
// f1 RESIDENT (filled once, reused across the 3 di's):
//   f1s [c32][xl24][q5] quads = 3840 q = 61440 B; xg = x2g0 + xl - 4, zero-pad
// f2 double-buffered, 4 phases x 8 channels per di, pipeline continues across di:
//   f2 buf [c8][x2 16][13 quads] = 1664 q = 26624 B each; guard quads 0 & 6 zero
// smem = 61440 + 2*26624 = 114688 B (112 KB) -> 2 blocks/SM
#define F2B 26624
#define F2BASE 61440          // bytes
#define F2BASEQ 3840          // quads
#define CADV 1024000          // 8 channels * 128000 floats

__global__ void __launch_bounds__(240, 2) corr_kernel(
    const float* __restrict__ f1, const float* __restrict__ f2, float* __restrict__ out)
{
    extern __shared__ float smem[];
    const unsigned sb = (unsigned)__cvta_generic_to_shared(smem);

    const int x2b  = blockIdx.x;
    const int y    = blockIdx.y;
    const int dig  = blockIdx.z;
    const int x2g0 = x2b * 16 - 4;
    const int y2_0 = y + dig * 3 - 4;          // y2 at dil=0
    const int tid  = threadIdx.x;

    const int zq  = tid % 5;
    const int x2c = (tid / 5) & 15;
    const int djg = tid / 80;
    const int x2g = x2g0 + x2c;

    const bool anyok = (y2_0 + 2 >= 0) && (y2_0 < 80);

    // ---- f2 fill slots: y-independent base + validity ----
    int f2base[3]; unsigned f2dst[3]; bool f2ok[3];
    #pragma unroll
    for (int k = 0; k < 3; ++k) {
        int j = tid + 240 * k;              // 0..639 copies
        int i = j / 5;
        int m = j - i * 5;
        int c   = i >> 4;
        int x2l = i & 15;
        int x2  = x2g0 + x2l;
        f2dst[k]  = sb + F2BASE + ((c * 16 + x2l) * 13 + 1 + m) * 16;
        f2ok[k]   = (j < 640) && ((unsigned)x2 < 80u);
        f2base[k] = c * 128000 + x2 * 20 + 4 * m;
    }

    // ---- zeroing (once per block) ----
    if (anyok) {
        float4 z4 = make_float4(0.f, 0.f, 0.f, 0.f);
        if (x2b == 0 || x2b == 5) {
            for (int i = tid; i < 7168; i += 240) ((float4*)smem)[i] = z4;
        } else {
            for (int i = tid; i < 512; i += 240) {
                int e   = i & 255;
                int cx  = e >> 1;
                int g   = (e & 1) * 6;
                int quad = F2BASEQ + (i >> 8) * (F2B / 16) + cx * 13 + g;
                ((float4*)smem)[quad] = z4;
            }
        }
    }
    __syncthreads();

    // ---- prologue: full f1 tile once + first valid di's f2 phase 0 ----
    if (anyok) {
        #pragma unroll
        for (int k = 0; k < 16; ++k) {
            int idx = tid + 240 * k;        // 0..3839 quads
            int c  = idx / 120;
            int r  = idx - c * 120;
            int xl = r / 5;
            int q  = r - xl * 5;
            int xg = x2g0 + xl - 4;
            if ((unsigned)xg < 80u)
                cp16(sb + idx * 16,
                     f1 + c * 128000 + y * 1600 + xg * 20 + 4 * q);
        }
        int fd = (y2_0 < 0) ? -y2_0 : 0;    // first valid dil
        int yf = y2_0 + fd;
        if (f2ok[0]) cp16(f2dst[0], f2 + f2base[0] + yf * 1600);
        if (f2ok[1]) cp16(f2dst[1], f2 + f2base[1] + yf * 1600);
        if (f2ok[2]) cp16(f2dst[2], f2 + f2base[2] + yf * 1600);
    }
    cp_commit();

    const int aq0 = (x2c + 8 - djg * 3) * 5 + zq;   // f1 quad idx (jl subtracts 5)
    const int bq0 = x2c * 13 + zq;                  // f2 quad idx within channel

    int g = 0;   // processed-phase counter (parity = buffer select)

    #pragma unroll 1
    for (int dil = 0; dil < 3; ++dil) {
        const int y2 = y2_0 + dil;
        const bool yok = ((unsigned)y2 < 80u);

        ull acc[30];
        #pragma unroll
        for (int i = 0; i < 30; ++i) acc[i] = 0ull;

        if (yok) {
            #pragma unroll 2
            for (int p = 0; p < 4; ++p) {
                const int cur = g & 1;
                cp_wait<0>();
                __syncthreads();
                // issue next fills into buf[(g+1)&1] (overlaps compute of phase p)
                {
                    const unsigned b2 = ((g + 1) & 1) * F2B;
                    if (p < 3) {
                        const int adv = y2 * 1600 + (p + 1) * CADV;
                        if (f2ok[0]) cp16(f2dst[0] + b2, f2 + f2base[0] + adv);
                        if (f2ok[1]) cp16(f2dst[1] + b2, f2 + f2base[1] + adv);
                        if (f2ok[2]) cp16(f2dst[2] + b2, f2 + f2base[2] + adv);
                    } else {
                        int nd = dil + 1;
                        int ny = y2 + 1;
                        if (nd < 3 && ny >= 80) { nd = 3; }   // past end
                        if (nd < 3 && ny < 0)   { nd++; ny++; }
                        if (nd < 3) {
                            const int adv = ny * 1600;
                            if (f2ok[0]) cp16(f2dst[0] + b2, f2 + f2base[0] + adv);
                            if (f2ok[1]) cp16(f2dst[1] + b2, f2 + f2base[1] + adv);
                            if (f2ok[2]) cp16(f2dst[2] + b2, f2 + f2base[2] + adv);
                        }
                    }
                    cp_commit();
                }
                // ---- compute phase p from buf[cur] ----
                const float* f1p = smem + p * 3840;   // 8 channels of this phase
                const float* f2b = smem + (F2BASE + cur * F2B) / 4;
                BW B0, B1;
                ulonglong2 A0, A1, A2;
                loadB(B0, f2b, 0, bq0);
                A0 = loadA(f1p, 0, aq0);
                A1 = loadA(f1p, 0, aq0 - 5);
                A2 = loadA(f1p, 0, aq0 - 10);
                loadB(B1, f2b, 1, bq0);
                #pragma unroll
                for (int cl = 0; cl < 8; ++cl) {
                    const BW& Bc = (cl & 1) ? B1 : B0;
                    ull P1 = shiftpair(Bc.q0hi, Bc.Q1.x);
                    ull P3 = shiftpair(Bc.Q1.x, Bc.Q1.y);
                    ull P5 = shiftpair(Bc.Q1.y, Bc.q2lo);
                    fma10(acc +  0, A0, Bc, P1, P3, P5);
                    if (cl < 7) A0 = loadA(f1p, cl + 1, aq0);
                    fma10(acc + 10, A1, Bc, P1, P3, P5);
                    if (cl < 7) A1 = loadA(f1p, cl + 1, aq0 - 5);
                    fma10(acc + 20, A2, Bc, P1, P3, P5);
                    if (cl < 7) A2 = loadA(f1p, cl + 1, aq0 - 10);
                    if (cl < 6) loadB((cl & 1) ? B1 : B0, f2b, cl + 2, bq0);
                }
                ++g;
            }
        }

        // ---- epilogue for this di (overlaps next di's in-flight fills) ----
        {
            const int di = dig * 3 + dil;
            const bool x2ok = ((unsigned)x2g < 80u);
            const bool spin = yok && x2ok;
            const float m2v = spin ? g_mask2[y2 * 80 + x2g] : 1.f;
            const float inv = 1.f / 32.f;
            #pragma unroll
            for (int jl = 0; jl < 3; ++jl) {
                const int dj = djg * 3 + jl;
                const int x  = x2g + 4 - dj;
                if ((unsigned)x < 80u) {
                    const float m1  = g_mask1[y * 80 + x];
                    const float mIn = m1 * m2v;
                    float* pc = out + (size_t)(di * 9 + dj) * 128000
                                    + y * 1600 + x * 20 + 4 * zq;
                    float* pm = pc + NTOT;
                    #pragma unroll
                    for (int dk = 0; dk < 5; ++dk) {
                        float4 cv;
                        unpack2(acc[jl * 10 + dk * 2 + 0], cv.x, cv.y);
                        unpack2(acc[jl * 10 + dk * 2 + 1], cv.z, cv.w);
                        cv.x *= inv; cv.y *= inv; cv.z *= inv; cv.w *= inv;
                        *(float4*)pc = cv;
                        float4 mv;
                        {
                            float* mp = (float*)&mv;
                            #pragma unroll
                            for (int zl = 0; zl < 4; ++zl) {
                                int z2 = 4 * zq + zl + dk - 2;
                                mp[zl] = ((unsigned)z2 < 20u) ? mIn : m1;
                            }
                        }
                        *(float4*)pm = mv;
                        pc += (size_t)81 * 128000;
                        pm += (size_t)81 * 128000;
                    }
                }
            }
        }
    }
}

extern "C" void kernel_launch(void* const* d_in, const int* in_sizes, int n_in,
                              void* d_out, int out_size)
{
    (void)in_sizes; (void)n_in; (void)out_size;
    const float* f1 = (const float*)d_in[0];
    const float* a1 = (const float*)d_in[1];
    const float* f2 = (const float*)d_in[2];
    const float* a2 = (const float*)d_in[3];
    float* out = (float*)d_out;

    cudaFuncSetAttribute(corr_kernel, cudaFuncAttributeMaxDynamicSharedMemorySize, 114688);

    mask_prep<<<25, 256>>>(a1, a2);
    corr_kernel<<<dim3(6, 80, 3), 240, 114688>>>(f1, f2, out);
}

// round 16
// speedup vs baseline: 1.0283x; 1.0014x over previous
#include <cuda_runtime.h>

typedef unsigned long long ull;

#define NTOT 51840000   // 405*80*80*20

__device__ float g_mask1[6400];
__device__ float g_mask2[6400];

__global__ void mask_prep(const float* __restrict__ a1, const float* __restrict__ a2)
{
    int p = blockIdx.x * blockDim.x + threadIdx.x;
    if (p < 6400) {
        float s1 = 0.f, s2 = 0.f;
        const float* p1 = a1 + p * 20;
        const float* p2 = a2 + p * 20;
        #pragma unroll
        for (int z = 0; z < 20; ++z) { s1 += p1[z]; s2 += p2[z]; }
        g_mask1[p] = fminf(fmaxf(s1, 0.f), 1.f);
        g_mask2[p] = fminf(fmaxf(s2, 0.f), 1.f);
    }
}

__device__ __forceinline__ void unpack2(ull v, float& lo, float& hi) {
    asm("mov.b64 {%0, %1}, %2;" : "=f"(lo), "=f"(hi) : "l"(v));
}
__device__ __forceinline__ void fma2(ull& d, ull a, ull b) {
    asm("fma.rn.f32x2 %0, %1, %2, %0;" : "+l"(d) : "l"(a), "l"(b));
}
__device__ __forceinline__ ull shiftpair(ull a, ull b) {
    ull r;
    asm("{\n\t.reg .b32 alo, ahi, blo, bhi;\n\t"
        "mov.b64 {alo, ahi}, %1;\n\t"
        "mov.b64 {blo, bhi}, %2;\n\t"
        "mov.b64 %0, {ahi, blo};\n\t}"
        : "=l"(r) : "l"(a), "l"(b));
    return r;
}
__device__ __forceinline__ void cp16(unsigned dst, const void* src) {
    asm volatile("cp.async.cg.shared.global [%0], [%1], 16;" :: "r"(dst), "l"(src));
}
__device__ __forceinline__ void cp_commit() {
    asm volatile("cp.async.commit_group;" ::: "memory");
}
template<int N> __device__ __forceinline__ void cp_wait() {
    asm volatile("cp.async.wait_group %0;" :: "n"(N) : "memory");
}

// b-window for one channel (8 regs)
struct BW {
    ull q0hi;         // z 4zq-2..4zq-1
    ulonglong2 Q1;    // z 4zq..4zq+3
    ull q2lo;         // z 4zq+4..4zq+5
};

__device__ __forceinline__ void loadB(BW& b, const float* f2b, int cl, int bq0)
{
    const float* bp = f2b + (cl * 208 + bq0) * 4;
    b.q0hi = *(const ull*)(bp + 2);
    b.Q1   = *(const ulonglong2*)(bp + 4);
    b.q2lo = *(const ull*)(bp + 8);
}
__device__ __forceinline__ ulonglong2 loadA(const float* f1p, int cl, int aq)
{
    return *(const ulonglong2*)(f1p + (cl * 120 + aq) * 4);
}

// 10 fma2 for one (channel, jl), ordered for operand-reuse adjacency:
// 5 consecutive FFMA2 share a.x, then 5 share a.y (collector-cached operand
// => 2 distinct even + 2 odd banks per instr => rt=2 instead of 3).
__device__ __forceinline__ void fma10(ull* A, ulonglong2 a, const BW& b,
                                      ull P1, ull P3, ull P5)
{
    fma2(A[0], a.x, b.q0hi);   // dk=0, p=0
    fma2(A[2], a.x, P1    );   // dk=1, p=0
    fma2(A[4], a.x, b.Q1.x);   // dk=2, p=0
    fma2(A[6], a.x, P3    );   // dk=3, p=0
    fma2(A[8], a.x, b.Q1.y);   // dk=4, p=0
    fma2(A[1], a.y, b.Q1.x);   // dk=0, p=1
    fma2(A[3], a.y, P3    );   // dk=1, p=1
    fma2(A[5], a.y, b.Q1.y);   // dk=2, p=1
    fma2(A[7], a.y, P5    );   // dk=3, p=1
    fma2(A[9], a.y, b.q2lo);   // dk=4, p=1
}

// block: 240 threads, tid = zq + 5*x2c + 80*djg (zq fastest -> coalesced stores)
// grid : (x2b 6, y 80, dig 3); block loops dil 0..2, di = dig*3 + dil
// f1 RESIDENT (filled once, reused across the 3 di's):
//   f1s [c32][xl24][q5] quads = 3840 q = 61440 B; xg = x2g0 + xl - 4, zero-pad
// f2 double-buffered, 4 phases x 8 channels per di, pipeline continues across di:
//   f2 buf [c8][x2 16][13 quads] = 1664 q = 26624 B each; guard quads 0 & 6 zero
// smem = 61440 + 2*26624 = 114688 B (112 KB) -> 2 blocks/SM
#define F2B 26624
#define F2BASE 61440          // bytes
#define F2BASEQ 3840          // quads
#define CADV 1024000          // 8 channels * 128000 floats

__global__ void __launch_bounds__(240, 2) corr_kernel(
    const float* __restrict__ f1, const float* __restrict__ f2, float* __restrict__ out)
{
    extern __shared__ float smem[];
    const unsigned sb = (unsigned)__cvta_generic_to_shared(smem);

    const int x2b  = blockIdx.x;
    const int y    = blockIdx.y;
    const int dig  = blockIdx.z;
    const int x2g0 = x2b * 16 - 4;
    const int y2_0 = y + dig * 3 - 4;          // y2 at dil=0
    const int tid  = threadIdx.x;

    const int zq  = tid % 5;
    const int x2c = (tid / 5) & 15;
    const int djg = tid / 80;
    const int x2g = x2g0 + x2c;

    const bool anyok = (y2_0 + 2 >= 0) && (y2_0 < 80);

    // ---- f2 fill slots: y-independent base + validity ----
    int f2base[3]; unsigned f2dst[3]; bool f2ok[3];
    #pragma unroll
    for (int k = 0; k < 3; ++k) {
        int j = tid + 240 * k;              // 0..639 copies
        int i = j / 5;
        int m = j - i * 5;
        int c   = i >> 4;
        int x2l = i & 15;
        int x2  = x2g0 + x2l;
        f2dst[k]  = sb + F2BASE + ((c * 16 + x2l) * 13 + 1 + m) * 16;
        f2ok[k]   = (j < 640) && ((unsigned)x2 < 80u);
        f2base[k] = c * 128000 + x2 * 20 + 4 * m;
    }

    // ---- zeroing (once per block) ----
    if (anyok) {
        float4 z4 = make_float4(0.f, 0.f, 0.f, 0.f);
        if (x2b == 0 || x2b == 5) {
            for (int i = tid; i < 7168; i += 240) ((float4*)smem)[i] = z4;
        } else {
            for (int i = tid; i < 512; i += 240) {
                int e   = i & 255;
                int cx  = e >> 1;
                int g   = (e & 1) * 6;
                int quad = F2BASEQ + (i >> 8) * (F2B / 16) + cx * 13 + g;
                ((float4*)smem)[quad] = z4;
            }
        }
    }
    __syncthreads();

    // ---- prologue: full f1 tile once + first valid di's f2 phase 0 ----
    if (anyok) {
        #pragma unroll
        for (int k = 0; k < 16; ++k) {
            int idx = tid + 240 * k;        // 0..3839 quads
            int c  = idx / 120;
            int r  = idx - c * 120;
            int xl = r / 5;
            int q  = r - xl * 5;
            int xg = x2g0 + xl - 4;
            if ((unsigned)xg < 80u)
                cp16(sb + idx * 16,
                     f1 + c * 128000 + y * 1600 + xg * 20 + 4 * q);
        }
        int fd = (y2_0 < 0) ? -y2_0 : 0;    // first valid dil
        int yf = y2_0 + fd;
        if (f2ok[0]) cp16(f2dst[0], f2 + f2base[0] + yf * 1600);
        if (f2ok[1]) cp16(f2dst[1], f2 + f2base[1] + yf * 1600);
        if (f2ok[2]) cp16(f2dst[2], f2 + f2base[2] + yf * 1600);
    }
    cp_commit();

    const int aq0 = (x2c + 8 - djg * 3) * 5 + zq;   // f1 quad idx (jl subtracts 5)
    const int bq0 = x2c * 13 + zq;                  // f2 quad idx within channel

    int g = 0;   // processed-phase counter (parity = buffer select)

    #pragma unroll 1
    for (int dil = 0; dil < 3; ++dil) {
        const int y2 = y2_0 + dil;
        const bool yok = ((unsigned)y2 < 80u);

        ull acc[30];
        #pragma unroll
        for (int i = 0; i < 30; ++i) acc[i] = 0ull;

        if (yok) {
            #pragma unroll 2
            for (int p = 0; p < 4; ++p) {
                const int cur = g & 1;
                cp_wait<0>();
                __syncthreads();
                // issue next fills into buf[(g+1)&1] (overlaps compute of phase p)
                {
                    const unsigned b2 = ((g + 1) & 1) * F2B;
                    if (p < 3) {
                        const int adv = y2 * 1600 + (p + 1) * CADV;
                        if (f2ok[0]) cp16(f2dst[0] + b2, f2 + f2base[0] + adv);
                        if (f2ok[1]) cp16(f2dst[1] + b2, f2 + f2base[1] + adv);
                        if (f2ok[2]) cp16(f2dst[2] + b2, f2 + f2base[2] + adv);
                    } else {
                        int nd = dil + 1;
                        int ny = y2 + 1;
                        if (nd < 3 && ny >= 80) { nd = 3; }   // past end
                        if (nd < 3 && ny < 0)   { nd++; ny++; }
                        if (nd < 3) {
                            const int adv = ny * 1600;
                            if (f2ok[0]) cp16(f2dst[0] + b2, f2 + f2base[0] + adv);
                            if (f2ok[1]) cp16(f2dst[1] + b2, f2 + f2base[1] + adv);
                            if (f2ok[2]) cp16(f2dst[2] + b2, f2 + f2base[2] + adv);
                        }
                    }
                    cp_commit();
                }
                // ---- compute phase p from buf[cur] ----
                const float* f1p = smem + p * 3840;   // 8 channels of this phase
                const float* f2b = smem + (F2BASE + cur * F2B) / 4;
                BW B0, B1;
                ulonglong2 A0, A1, A2;
                loadB(B0, f2b, 0, bq0);
                A0 = loadA(f1p, 0, aq0);
                A1 = loadA(f1p, 0, aq0 - 5);
                A2 = loadA(f1p, 0, aq0 - 10);
                loadB(B1, f2b, 1, bq0);
                #pragma unroll
                for (int cl = 0; cl < 8; ++cl) {
                    const BW& Bc = (cl & 1) ? B1 : B0;
                    ull P1 = shiftpair(Bc.q0hi, Bc.Q1.x);
                    ull P3 = shiftpair(Bc.Q1.x, Bc.Q1.y);
                    ull P5 = shiftpair(Bc.Q1.y, Bc.q2lo);
                    fma10(acc +  0, A0, Bc, P1, P3, P5);
                    if (cl < 7) A0 = loadA(f1p, cl + 1, aq0);
                    fma10(acc + 10, A1, Bc, P1, P3, P5);
                    if (cl < 7) A1 = loadA(f1p, cl + 1, aq0 - 5);
                    fma10(acc + 20, A2, Bc, P1, P3, P5);
                    if (cl < 7) A2 = loadA(f1p, cl + 1, aq0 - 10);
                    if (cl < 6) loadB((cl & 1) ? B1 : B0, f2b, cl + 2, bq0);
                }
                ++g;
            }
        }

        // ---- epilogue for this di (overlaps next di's in-flight fills) ----
        {
            const int di = dig * 3 + dil;
            const bool x2ok = ((unsigned)x2g < 80u);
            const bool spin = yok && x2ok;
            const float m2v = spin ? g_mask2[y2 * 80 + x2g] : 1.f;
            const float inv = 1.f / 32.f;
            #pragma unroll
            for (int jl = 0; jl < 3; ++jl) {
                const int dj = djg * 3 + jl;
                const int x  = x2g + 4 - dj;
                if ((unsigned)x < 80u) {
                    const float m1  = g_mask1[y * 80 + x];
                    const float mIn = m1 * m2v;
                    float* pc = out + (size_t)(di * 9 + dj) * 128000
                                    + y * 1600 + x * 20 + 4 * zq;
                    float* pm = pc + NTOT;
                    #pragma unroll
                    for (int dk = 0; dk < 5; ++dk) {
                        float4 cv;
                        unpack2(acc[jl * 10 + dk * 2 + 0], cv.x, cv.y);
                        unpack2(acc[jl * 10 + dk * 2 + 1], cv.z, cv.w);
                        cv.x *= inv; cv.y *= inv; cv.z *= inv; cv.w *= inv;
                        *(float4*)pc = cv;
                        float4 mv;
                        {
                            float* mp = (float*)&mv;
                            #pragma unroll
                            for (int zl = 0; zl < 4; ++zl) {
                                int z2 = 4 * zq + zl + dk - 2;
                                mp[zl] = ((unsigned)z2 < 20u) ? mIn : m1;
                            }
                        }
                        *(float4*)pm = mv;
                        pc += (size_t)81 * 128000;
                        pm += (size_t)81 * 128000;
                    }
                }
            }
        }
    }
}

extern "C" void kernel_launch(void* const* d_in, const int* in_sizes, int n_in,
                              void* d_out, int out_size)
{
    (void)in_sizes; (void)n_in; (void)out_size;
    const float* f1 = (const float*)d_in[0];
    const float* a1 = (const float*)d_in[1];
    const float* f2 = (const float*)d_in[2];
    const float* a2 = (const float*)d_in[3];
    float* out = (float*)d_out;

    cudaFuncSetAttribute(corr_kernel, cudaFuncAttributeMaxDynamicSharedMemorySize, 114688);

    mask_prep<<<25, 256>>>(a1, a2);
    corr_kernel<<<dim3(6, 80, 3), 240, 114688>>>(f1, f2, out);
}